// round 1
// baseline (speedup 1.0000x reference)
#include <cuda_runtime.h>

#define T_ 512
#define B_ 64
#define I_ 512
#define H_ 512

// ---------------- scratch (static device globals; no allocation allowed) ----
__device__ float g_xproj[2][T_][B_][H_];   // 134 MB: input projections per dir
__device__ float g_hx[2][2][B_][H_];       // h exchange, double-buffered by parity
__device__ int   g_flag[2][8][8];          // per (dir, batch-group, cta) step flags

// ---------------- init: zero flags each launch (graph-replay determinism) ---
__global__ void zero_flags_kernel() {
    int i = threadIdx.x;
    if (i < 128) ((int*)g_flag)[i] = 0;
}

// ---------------- Phase 1: xproj GEMM  (M=32768, N=512 per dir, K=512) ------
// C[m][n] = sum_k x[m][k] * W[n][k] + bias[n], stored as g_xproj[dir][t][b][j]
__global__ __launch_bounds__(256) void xproj_kernel(
    const float* __restrict__ x,
    const float* __restrict__ Wf, const float* __restrict__ bf,
    const float* __restrict__ Wb, const float* __restrict__ bb)
{
    __shared__ __align__(16) float As[16][132];
    __shared__ __align__(16) float Bs[16][68];

    const int dir = blockIdx.z;
    const float* __restrict__ W    = dir ? Wb : Wf;
    const float* __restrict__ bias = dir ? bb : bf;
    float* __restrict__ out = &g_xproj[dir][0][0][0];

    const int n0 = blockIdx.x * 64;
    const int m0 = blockIdx.y * 128;
    const int tid = threadIdx.x;
    const int tx = tid & 15;        // n sub-tile (x4)
    const int ty = tid >> 4;        // m sub-tile (x8)
    const int lr = tid >> 2;        // load row 0..63
    const int lk = (tid & 3) * 4;   // load k 0..12

    float acc[8][4];
#pragma unroll
    for (int i = 0; i < 8; i++)
#pragma unroll
        for (int j = 0; j < 4; j++) acc[i][j] = 0.f;

    for (int kt = 0; kt < I_; kt += 16) {
        float4 a0 = *(const float4*)(x + (size_t)(m0 + lr)      * I_ + kt + lk);
        float4 a1 = *(const float4*)(x + (size_t)(m0 + lr + 64) * I_ + kt + lk);
        float4 bv = *(const float4*)(W + (size_t)(n0 + lr)      * I_ + kt + lk);
        As[lk + 0][lr]      = a0.x; As[lk + 1][lr]      = a0.y;
        As[lk + 2][lr]      = a0.z; As[lk + 3][lr]      = a0.w;
        As[lk + 0][lr + 64] = a1.x; As[lk + 1][lr + 64] = a1.y;
        As[lk + 2][lr + 64] = a1.z; As[lk + 3][lr + 64] = a1.w;
        Bs[lk + 0][lr] = bv.x; Bs[lk + 1][lr] = bv.y;
        Bs[lk + 2][lr] = bv.z; Bs[lk + 3][lr] = bv.w;
        __syncthreads();
#pragma unroll
        for (int k = 0; k < 16; k++) {
            float4 av0 = *(const float4*)&As[k][ty * 8];
            float4 av1 = *(const float4*)&As[k][ty * 8 + 4];
            float4 bv4 = *(const float4*)&Bs[k][tx * 4];
            float am[8] = {av0.x, av0.y, av0.z, av0.w, av1.x, av1.y, av1.z, av1.w};
            float bn[4] = {bv4.x, bv4.y, bv4.z, bv4.w};
#pragma unroll
            for (int i = 0; i < 8; i++)
#pragma unroll
                for (int j = 0; j < 4; j++)
                    acc[i][j] += am[i] * bn[j];
        }
        __syncthreads();
    }

    float4 b4 = *(const float4*)(bias + n0 + tx * 4);
    const int bb_ = m0 >> 9;                 // batch (constant within 128-row tile)
    const int tbase = (m0 & 511) + ty * 8;   // time index base
#pragma unroll
    for (int i = 0; i < 8; i++) {
        int t = tbase + i;
        float4 o;
        o.x = acc[i][0] + b4.x; o.y = acc[i][1] + b4.y;
        o.z = acc[i][2] + b4.z; o.w = acc[i][3] + b4.w;
        *(float4*)(out + ((size_t)t * B_ + bb_) * H_ + n0 + tx * 4) = o;
    }
}

// ---------------- Phase 2: persistent recurrence ----------------------------
// 128 CTAs = 2 dirs x 8 batch-groups x 8 j-slice CTAs. Each CTA holds its
// 64x512 Wh slice (transposed, padded) + h state for 8 batches in SMEM.
// Per step: partial GEMM (k split across 16 warps) -> SMEM reduce -> tanh ->
// L2 h-slice exchange with flag barrier within the 8-CTA group.

#define SMEM_WHS   (512 * 65)                 // Whs_T[k][jj], pad 65 -> no conflicts
#define SMEM_HCUR  (8 * 512)
#define SMEM_RED   (16 * 512)
#define SMEM_FLOATS (SMEM_WHS + SMEM_HCUR + SMEM_RED)
#define SMEM_BYTES  (SMEM_FLOATS * 4)         // 182272 B

__global__ void __launch_bounds__(512, 1) rnn_kernel(
    const float* __restrict__ h0f, const float* __restrict__ h0b,
    const float* __restrict__ Whf, const float* __restrict__ Whb,
    float* __restrict__ y, float* __restrict__ hTf, float* __restrict__ hTb)
{
    extern __shared__ __align__(16) float smem[];
    float* Whs  = smem;                         // [512][65]
    float* hcur = smem + SMEM_WHS;              // [8][512]
    float* red  = smem + SMEM_WHS + SMEM_HCUR;  // [16][512]

    const int tid = threadIdx.x;
    const int c   = blockIdx.x & 7;       // j-slice cta within group
    const int grp = blockIdx.x >> 3;
    const int dir = grp >> 3;
    const int bg  = grp & 7;
    const int b0  = bg * 8;
    const int j0  = c * 64;

    const float* __restrict__ Wh = dir ? Whb : Whf;
    const float* __restrict__ h0 = dir ? h0b : h0f;
    const float* __restrict__ xp_base = &g_xproj[dir][0][0][0];
    float* __restrict__ hxd = &g_hx[dir][0][0][0];   // [2][64][512]
    int* flags = &g_flag[dir][bg][0];

    // Load Wh slice transposed: Whs[k*65 + jj] = Wh[j0+jj][k]
    for (int idx = tid; idx < 64 * 512; idx += 512) {
        int jj = idx >> 9;           // 0..63
        int k  = idx & 511;          // == tid
        Whs[k * 65 + jj] = Wh[(size_t)(j0 + jj) * H_ + k];
    }
    // Load initial h for our 8 batches
    {
        const float4* src = (const float4*)(h0 + (size_t)b0 * H_);
        float4* dst = (float4*)hcur;
        dst[tid]       = src[tid];
        dst[tid + 512] = src[tid + 512];
    }
    __syncthreads();

    const int lane = tid & 31;
    const int w    = tid >> 5;     // 16 warps, k-chunk of 32 each
    const int k0   = w * 32;
    const int pb   = tid >> 6;     // batch 0..7 for reduce/store
    const int pj   = tid & 63;     // local j 0..63

    for (int s = 0; s < T_; s++) {
        const int t = dir ? (T_ - 1 - s) : s;

        float acc0[8], acc1[8];
#pragma unroll
        for (int b = 0; b < 8; b++) { acc0[b] = 0.f; acc1[b] = 0.f; }

        const float4* h4 = (const float4*)hcur;
#pragma unroll
        for (int kb = 0; kb < 8; kb++) {
            const int kk = k0 + kb * 4;
            float wa0 = Whs[(kk + 0) * 65 + lane];
            float wa1 = Whs[(kk + 1) * 65 + lane];
            float wa2 = Whs[(kk + 2) * 65 + lane];
            float wa3 = Whs[(kk + 3) * 65 + lane];
            float wb0 = Whs[(kk + 0) * 65 + lane + 32];
            float wb1 = Whs[(kk + 1) * 65 + lane + 32];
            float wb2 = Whs[(kk + 2) * 65 + lane + 32];
            float wb3 = Whs[(kk + 3) * 65 + lane + 32];
#pragma unroll
            for (int b = 0; b < 8; b++) {
                float4 hv = h4[b * 128 + (kk >> 2)];   // broadcast across warp
                acc0[b] += hv.x * wa0; acc0[b] += hv.y * wa1;
                acc0[b] += hv.z * wa2; acc0[b] += hv.w * wa3;
                acc1[b] += hv.x * wb0; acc1[b] += hv.y * wb1;
                acc1[b] += hv.z * wb2; acc1[b] += hv.w * wb3;
            }
        }

        // start xp load early (L2 latency overlap with reduction)
        float xpv = xp_base[((size_t)t * B_ + b0 + pb) * H_ + j0 + pj];

#pragma unroll
        for (int b = 0; b < 8; b++) {
            red[w * 512 + b * 64 + lane]      = acc0[b];
            red[w * 512 + b * 64 + lane + 32] = acc1[b];
        }
        __syncthreads();

        float v = 0.f;
#pragma unroll
        for (int ww = 0; ww < 16; ww++) v += red[ww * 512 + tid];

        float hn = tanhf(xpv + v);

        const int p2 = (s + 1) & 1;
        // y output: (B, T, 2H)
        y[((size_t)(b0 + pb) * T_ + t) * (2 * H_) + dir * H_ + j0 + pj] = hn;
        // h exchange (L2, bypass L1)
        __stcg(&hxd[((size_t)p2 * B_ + b0 + pb) * H_ + j0 + pj], hn);
        if (s == T_ - 1) {
            (dir ? hTb : hTf)[(size_t)(b0 + pb) * H_ + j0 + pj] = hn;
        }

        __threadfence();          // make st.cg visible (cumulative via bar below)
        __syncthreads();
        if (tid == 0) atomicExch(&flags[c], s + 1);

        if (tid < 8) {
            const int target = s + 1;
            int fv;
            do {
                asm volatile("ld.global.cg.u32 %0, [%1];" : "=r"(fv) : "l"(&flags[tid]));
                if (fv >= target) break;
                __nanosleep(64);
            } while (true);
        }
        __syncthreads();

        // Reload full h for our 8 batches from the exchange buffer
        {
            const float4* src = (const float4*)&hxd[((size_t)p2 * B_ + b0) * H_];
            float4 v0 = __ldcg(&src[tid]);
            float4 v1 = __ldcg(&src[tid + 512]);
            float4* dst = (float4*)hcur;
            dst[tid]       = v0;
            dst[tid + 512] = v1;
        }
        __syncthreads();
    }
}

// ---------------- launch -----------------------------------------------------
extern "C" void kernel_launch(void* const* d_in, const int* in_sizes, int n_in,
                              void* d_out, int out_size)
{
    (void)in_sizes; (void)n_in; (void)out_size;
    const float* x   = (const float*)d_in[0];
    const float* h0f = (const float*)d_in[1];
    const float* h0b = (const float*)d_in[2];
    const float* Wxf = (const float*)d_in[3];
    const float* bxf = (const float*)d_in[4];
    const float* Whf = (const float*)d_in[5];
    const float* Wxb = (const float*)d_in[6];
    const float* bxb = (const float*)d_in[7];
    const float* Whb = (const float*)d_in[8];

    float* y   = (float*)d_out;                       // (B, T, 2H)
    float* hTf = y + (size_t)B_ * T_ * 2 * H_;        // (B, H)
    float* hTb = hTf + (size_t)B_ * H_;               // (B, H)

    cudaFuncSetAttribute(rnn_kernel, cudaFuncAttributeMaxDynamicSharedMemorySize,
                         SMEM_BYTES);

    zero_flags_kernel<<<1, 128>>>();

    dim3 gg(8, 256, 2);   // N/64, M/128, dir
    xproj_kernel<<<gg, 256>>>(x, Wxf, bxf, Wxb, bxb);

    rnn_kernel<<<128, 512, SMEM_BYTES>>>(h0f, h0b, Whf, Whb, y, hTf, hTb);
}